// round 15
// baseline (speedup 1.0000x reference)
#include <cuda_runtime.h>
#include <cuda_fp16.h>
#include <math.h>
#include <cstdint>

#define NB 32
#define NN 512

// Scratch (device globals; allocation-free per harness rules).
__device__ __align__(16) __half g_c16[(size_t)NB * NN * NN];  // fp16 c [m][k]
__device__ __align__(16) __half g_a16[(size_t)NB * NN * NN];  // fp16 a [j][n] row-major
__device__ __align__(16) float  g_G[(size_t)NB * NN * NN];    // G = c @ a (fp32, streamed)

// ---------------------------------------------------------------------------
__device__ __forceinline__ uint32_t smem_u32(const void* p) {
    uint32_t a;
    asm("{ .reg .u64 t; cvta.to.shared.u64 t, %1; cvt.u32.u64 %0, t; }" : "=r"(a) : "l"(p));
    return a;
}
__device__ __forceinline__ void cp_async16(uint32_t saddr, const void* gaddr) {
    asm volatile("cp.async.cg.shared.global [%0], [%1], 16;" :: "r"(saddr), "l"(gaddr) : "memory");
}
__device__ __forceinline__ void cp_commit() { asm volatile("cp.async.commit_group;" ::: "memory"); }
__device__ __forceinline__ void cp_wait6()  { asm volatile("cp.async.wait_group 6;" ::: "memory"); }
__device__ __forceinline__ void cp_wait0()  { asm volatile("cp.async.wait_group 0;" ::: "memory"); }
__device__ __forceinline__ void ldsm_x4(uint32_t* r, uint32_t addr) {
    asm volatile("ldmatrix.sync.aligned.m8n8.x4.shared.b16 {%0,%1,%2,%3}, [%4];"
                 : "=r"(r[0]), "=r"(r[1]), "=r"(r[2]), "=r"(r[3]) : "r"(addr));
}
__device__ __forceinline__ void ldsm_x4_t(uint32_t* r, uint32_t addr) {
    asm volatile("ldmatrix.sync.aligned.m8n8.x4.trans.shared.b16 {%0,%1,%2,%3}, [%4];"
                 : "=r"(r[0]), "=r"(r[1]), "=r"(r[2]), "=r"(r[3]) : "r"(addr));
}
__device__ __forceinline__ void mma_fp16(float* d, const uint32_t* a, const uint32_t* b) {
    asm volatile(
        "mma.sync.aligned.m16n8k16.row.col.f32.f16.f16.f32 "
        "{%0,%1,%2,%3}, {%4,%5,%6,%7}, {%8,%9}, {%0,%1,%2,%3};"
        : "+f"(d[0]), "+f"(d[1]), "+f"(d[2]), "+f"(d[3])
        : "r"(a[0]), "r"(a[1]), "r"(a[2]), "r"(a[3]), "r"(b[0]), "r"(b[1]));
}
__device__ __forceinline__ void stcs_f2(float* p, float2 v) {
    asm volatile("st.global.cs.v2.f32 [%0], {%1, %2};" :: "l"(p), "f"(v.x), "f"(v.y) : "memory");
}
__device__ __forceinline__ float4 ldcs_f4(const float* p) {
    float4 v;
    asm volatile("ld.global.cs.v4.f32 {%0,%1,%2,%3}, [%4];"
                 : "=f"(v.x), "=f"(v.y), "=f"(v.z), "=f"(v.w) : "l"(p));
    return v;
}

// temp arrives as 1-elem scalar, int32 or float32 bits; decode robustly.
__device__ __forceinline__ float decode_scalar(const int* p) {
    int ib = *p;
    float f = __int_as_float(ib);
    if (isfinite(f) && fabsf(f) > 1e-30f && fabsf(f) < 1e30f) return f;
    return (float)ib;
}

// ---------------------------------------------------------------------------
// Fused c + step0 (verbatim R13).
// ---------------------------------------------------------------------------
__global__ void __launch_bounds__(256) cstep0_kernel(
    const float* __restrict__ x, const float* __restrict__ w1,
    const float* __restrict__ b1, const float* __restrict__ w2,
    const float* __restrict__ lr, const int* __restrict__ temp_p)
{
    int b  = blockIdx.y;
    int i0 = blockIdx.x * 8;
    __shared__ float xs[NN];
    __shared__ float sw1a[16], sw1b[16], sb1[16], sw2[16];
    __shared__ float red[8];
    __shared__ float sS, sM, sT;
    const int t    = threadIdx.x;
    const int lane = t & 31;
    const int wid  = t >> 5;
    if (t < 16) {
        sw1a[t] = w1[t * 2 + 0];
        sw1b[t] = w1[t * 2 + 1];
        sb1[t]  = b1[t];
        sw2[t]  = w2[t];
    }
    xs[t]       = x[b * NN + t];
    xs[t + 256] = x[b * NN + t + 256];
    __syncthreads();

    const float lr_abs = fabsf(lr[0]);
    const float invT   = 1.f / decode_scalar(temp_p);
    const float invN   = 1.f / (float)NN;

    for (int ii = 0; ii < 8; ii++) {
        int i = i0 + ii;
        float xi = xs[i];
        size_t rowoff = ((size_t)b * NN + i) * NN;

        float sv[2];
#pragma unroll
        for (int q = 0; q < 2; q++) {
            float xj = xs[t + q * 256];
            float s = 0.f;
#pragma unroll
            for (int o = 0; o < 16; o++) {
                float h1 = fmaxf(fmaf(sw1a[o], xi, fmaf(sw1b[o], xj, sb1[o])), 0.f);
                float h2 = fmaxf(fmaf(sw1a[o], xj, fmaf(sw1b[o], xi, sb1[o])), 0.f);
                s = fmaf(sw2[o], h1 - h2, s);
            }
            __half h = __float2half(s);
            g_c16[rowoff + t + q * 256] = h;
            sv[q] = __half2float(h);
        }

        float v = sv[0] + sv[1];
#pragma unroll
        for (int o = 16; o > 0; o >>= 1) v += __shfl_xor_sync(0xffffffffu, v, o);
        if (lane == 0) red[wid] = v;
        __syncthreads();
        if (wid == 0) {
            float s8 = (lane < 8) ? red[lane] : 0.f;
#pragma unroll
            for (int o = 4; o > 0; o >>= 1) s8 += __shfl_xor_sync(0xffffffffu, s8, o);
            if (lane == 0) sS = s8;
        }
        __syncthreads();
        const float S = sS;

        float l0 = (invN - lr_abs * S * (1.f - (2.f * t + 1.f) * invN)) * invT;
        float l1 = (invN - lr_abs * S * (1.f - (2.f * (t + 256) + 1.f) * invN)) * invT;

        float m = fmaxf(l0, l1);
#pragma unroll
        for (int o = 16; o > 0; o >>= 1) m = fmaxf(m, __shfl_xor_sync(0xffffffffu, m, o));
        __syncthreads();
        if (lane == 0) red[wid] = m;
        __syncthreads();
        if (wid == 0) {
            float m8 = (lane < 8) ? red[lane] : -INFINITY;
#pragma unroll
            for (int o = 4; o > 0; o >>= 1) m8 = fmaxf(m8, __shfl_xor_sync(0xffffffffu, m8, o));
            if (lane == 0) sM = m8;
        }
        __syncthreads();
        const float M = sM;

        float e0 = __expf(l0 - M);
        float e1 = __expf(l1 - M);
        float se = e0 + e1;
#pragma unroll
        for (int o = 16; o > 0; o >>= 1) se += __shfl_xor_sync(0xffffffffu, se, o);
        __syncthreads();
        if (lane == 0) red[wid] = se;
        __syncthreads();
        if (wid == 0) {
            float t8 = (lane < 8) ? red[lane] : 0.f;
#pragma unroll
            for (int o = 4; o > 0; o >>= 1) t8 += __shfl_xor_sync(0xffffffffu, t8, o);
            if (lane == 0) sT = t8;
        }
        __syncthreads();
        const float invTot = 1.f / sT;

        g_a16[rowoff + t]       = __float2half(e0 * invTot);
        g_a16[rowoff + t + 256] = __float2half(e1 * invTot);
        __syncthreads();
    }
}

// ---------------------------------------------------------------------------
// Batched GEMM: G = c @ a, single-product fp16 mma.sync. (R8 body, minus
// the redundant trailing sync; G stored with streaming hint.)
// ---------------------------------------------------------------------------
#define PA 24
#define PB 136
#define A_TILE_B (128 * PA * 2)        // 6144 B
#define B_TILE_B (16 * PB * 2)         // 4352 B
#define STAGE_B  (A_TILE_B + B_TILE_B) // 10496
#define NSTAGE 8
#define GEMM_SMEM (NSTAGE * STAGE_B)   // 83968

__global__ void __launch_bounds__(128, 2) gemm_mma_kernel()
{
    extern __shared__ __align__(16) char sm[];
    const int b  = blockIdx.z;
    const int m0 = blockIdx.y * 128;
    const int n0 = blockIdx.x * 128;
    const int tid  = threadIdx.x;
    const int wid  = tid >> 5;
    const int lane = tid & 31;

    const __half* Amat = g_c16 + (size_t)b * NN * NN;
    const __half* Bmat = g_a16 + (size_t)b * NN * NN;

    const uint32_t smbase = smem_u32(sm);

    auto load_stage = [&](int ks16) {
        const int k0 = ks16 * 16;
        const uint32_t sb = smbase + (ks16 % NSTAGE) * STAGE_B;
#pragma unroll
        for (int it = 0; it < 2; it++) {
            int idx = it * 128 + tid;
            int r   = idx >> 1;
            int c   = idx & 1;
            cp_async16(sb + (uint32_t)(r * (PA * 2) + c * 16),
                       Amat + (size_t)(m0 + r) * NN + k0 + c * 8);
        }
#pragma unroll
        for (int it = 0; it < 2; it++) {
            int idx = it * 128 + tid;
            int r   = idx >> 4;
            int c   = idx & 15;
            cp_async16(sb + A_TILE_B + (uint32_t)(r * (PB * 2) + c * 16),
                       Bmat + (size_t)(k0 + r) * NN + n0 + c * 8);
        }
        cp_commit();
    };

    const int wm = wid & 1;
    const int wn = wid >> 1;

    float acc[4][8][4];
#pragma unroll
    for (int mi = 0; mi < 4; mi++)
#pragma unroll
        for (int ni = 0; ni < 8; ni++)
#pragma unroll
            for (int q = 0; q < 4; q++) acc[mi][ni][q] = 0.f;

    const int l_r = lane & 15;
    const int l_c = 8 * (lane >> 4);

#pragma unroll
    for (int s = 0; s < NSTAGE - 1; s++) load_stage(s);

    for (int s = 0; s < 32; s++) {
        cp_wait6();
        __syncthreads();

        const uint32_t sb = smbase + (s % NSTAGE) * STAGE_B;
        uint32_t ah[4][4];
#pragma unroll
        for (int mi = 0; mi < 4; mi++) {
            uint32_t addr = sb + (wm * 64 + mi * 16 + l_r) * (PA * 2) + l_c * 2;
            ldsm_x4(ah[mi], addr);
        }
        uint32_t bh[8][2];
#pragma unroll
        for (int nh = 0; nh < 2; nh++) {
#pragma unroll
            for (int t16 = 0; t16 < 2; t16++) {
                uint32_t addr = sb + A_TILE_B +
                                l_r * (PB * 2) + (wn * 64 + nh * 32 + t16 * 16 + l_c) * 2;
                uint32_t r4[4];
                ldsm_x4_t(r4, addr);
                int base = nh * 4 + t16 * 2;
                bh[base][0] = r4[0];     bh[base][1] = r4[1];
                bh[base + 1][0] = r4[2]; bh[base + 1][1] = r4[3];
            }
        }
#pragma unroll
        for (int mi = 0; mi < 4; mi++)
#pragma unroll
            for (int ni = 0; ni < 8; ni++)
                mma_fp16(acc[mi][ni], ah[mi], bh[ni]);

        // Safe without a trailing sync: load target buf (s+7)%8 was last read
        // in compute(s-1), and every warp passed the top sync of iter s after
        // finishing compute(s-1).
        if (s + NSTAGE - 1 < 32) load_stage(s + NSTAGE - 1);
    }
    cp_wait0();

    float* Gb = g_G + (size_t)b * NN * NN;
    const int g  = lane >> 2;
    const int t4 = lane & 3;
#pragma unroll
    for (int mi = 0; mi < 4; mi++) {
        int r0 = m0 + wm * 64 + mi * 16 + g;
#pragma unroll
        for (int ni = 0; ni < 8; ni++) {
            int col = n0 + wn * 64 + ni * 8 + t4 * 2;
            stcs_f2(Gb + (size_t)r0 * NN + col,
                    make_float2(acc[mi][ni][0], acc[mi][ni][1]));
            stcs_f2(Gb + (size_t)(r0 + 8) * NN + col,
                    make_float2(acc[mi][ni][2], acc[mi][ni][3]));
        }
    }
}

// ---------------------------------------------------------------------------
// Epilogue fused: warp per row; G read with streaming hint (read-once).
// Math verbatim R8.
// ---------------------------------------------------------------------------
__global__ void __launch_bounds__(256) epi_fuse_kernel(
    float* __restrict__ a_out, const float* __restrict__ lr,
    const int* __restrict__ temp_p, int last)
{
    const int row  = blockIdx.x * 8 + (threadIdx.x >> 5);
    const int lane = threadIdx.x & 31;
    const size_t base = (size_t)row * NN + lane * 16;
    const float* Gr = g_G + base;

    float g[16];
#pragma unroll
    for (int q = 0; q < 4; q++) {
        float4 vg = ldcs_f4(Gr + q * 4);
        g[q * 4 + 0] = vg.x; g[q * 4 + 1] = vg.y; g[q * 4 + 2] = vg.z; g[q * 4 + 3] = vg.w;
    }

    union U16 { uint4 u4[2]; __half h[16]; };
    U16 ua;
    ua.u4[0] = *(const uint4*)(g_a16 + base);
    ua.u4[1] = *(const uint4*)(g_a16 + base + 8);

    float av[16];
#pragma unroll
    for (int c = 0; c < 16; c++) av[c] = __half2float(ua.h[c]);

    float p[16];
    float run = 0.f;
#pragma unroll
    for (int c = 0; c < 16; c++) { run += g[c]; p[c] = run; }
    float inc = run;
#pragma unroll
    for (int o = 1; o < 32; o <<= 1) {
        float n = __shfl_up_sync(0xffffffffu, inc, o);
        if (lane >= o) inc += n;
    }
    const float excl = inc - run;

    const float lr_abs = fabsf(lr[0]);
    const float invT   = 1.f / decode_scalar(temp_p);

    float lo[16];
    float mx = -INFINITY;
#pragma unroll
    for (int c = 0; c < 16; c++) {
        float cum = excl + p[c];
        float l = (av[c] - lr_abs * (g[c] - 2.f * cum)) * invT;
        lo[c] = l;
        mx = fmaxf(mx, l);
    }
#pragma unroll
    for (int o = 16; o > 0; o >>= 1) mx = fmaxf(mx, __shfl_xor_sync(0xffffffffu, mx, o));

    float s = 0.f;
#pragma unroll
    for (int c = 0; c < 16; c++) { lo[c] = __expf(lo[c] - mx); s += lo[c]; }
#pragma unroll
    for (int o = 16; o > 0; o >>= 1) s += __shfl_xor_sync(0xffffffffu, s, o);
    const float invS = 1.f / s;

    U16 oa;
#pragma unroll
    for (int c = 0; c < 16; c++) {
        float v = lo[c] * invS;
        oa.h[c] = __float2half(v);
        lo[c] = v;
    }
    *(uint4*)(g_a16 + base)     = oa.u4[0];
    *(uint4*)(g_a16 + base + 8) = oa.u4[1];

    if (last) {
        float* ar = a_out + base;
#pragma unroll
        for (int q = 0; q < 4; q++) {
            stcs_f2(ar + q * 4,     make_float2(lo[q * 4 + 0], lo[q * 4 + 1]));
            stcs_f2(ar + q * 4 + 2, make_float2(lo[q * 4 + 2], lo[q * 4 + 3]));
        }
    }
}

// ---------------------------------------------------------------------------
// y[b,k] = sum_i x[b,i] * a[b,i,k]; 16 i-chunks per batch + atomicAdd.
// (verbatim R8 — measured-safe high-parallelism form)
// ---------------------------------------------------------------------------
__global__ void init_y_kernel(float* __restrict__ y)
{
    y[blockIdx.x * 1024 + threadIdx.x] = 0.f;
}

__global__ void __launch_bounds__(512) y_kernel(
    const float* __restrict__ x, const float* __restrict__ a, float* __restrict__ y)
{
    int b  = blockIdx.x;
    int ch = blockIdx.y;
    int k  = threadIdx.x;
    __shared__ float xs[32];
    if (k < 32) xs[k] = x[b * NN + ch * 32 + k];
    __syncthreads();
    const float* ab = a + (size_t)b * NN * NN + (size_t)ch * 32 * NN;
    float a0 = 0.f, a1 = 0.f, a2 = 0.f, a3 = 0.f;
#pragma unroll
    for (int i = 0; i < 32; i += 4) {
        a0 = fmaf(xs[i + 0], ab[(size_t)(i + 0) * NN + k], a0);
        a1 = fmaf(xs[i + 1], ab[(size_t)(i + 1) * NN + k], a1);
        a2 = fmaf(xs[i + 2], ab[(size_t)(i + 2) * NN + k], a2);
        a3 = fmaf(xs[i + 3], ab[(size_t)(i + 3) * NN + k], a3);
    }
    atomicAdd(&y[b * NN + k], (a0 + a1) + (a2 + a3));
}

// ---------------------------------------------------------------------------
extern "C" void kernel_launch(void* const* d_in, const int* in_sizes, int n_in,
                              void* d_out, int out_size)
{
    const float* x   = (const float*)d_in[0];
    const float* w1  = (const float*)d_in[1];
    const float* b1  = (const float*)d_in[2];
    const float* w2  = (const float*)d_in[3];
    // d_in[4] = b2 (cancels in c - c^T), d_in[6] = steps (fixed at 8)
    const float* lr  = (const float*)d_in[5];
    const int* temp_p = (const int*)d_in[7];

    float* y = (float*)d_out;              // (32,1,512)
    float* a = (float*)d_out + NB * NN;    // (32,512,512), written on last step

    cudaFuncSetAttribute(gemm_mma_kernel, cudaFuncAttributeMaxDynamicSharedMemorySize, GEMM_SMEM);

    cstep0_kernel<<<dim3(NN / 8, NB), 256>>>(x, w1, b1, w2, lr, temp_p);

    for (int s = 0; s < 7; s++) {
        gemm_mma_kernel<<<dim3(4, 4, NB), 128, GEMM_SMEM>>>();
        epi_fuse_kernel<<<NB * NN / 8, 256>>>(a, lr, temp_p, (s == 6) ? 1 : 0);
    }

    init_y_kernel<<<NB * NN / 1024, 1024>>>(y);
    y_kernel<<<dim3(NB, 16), 512>>>(x, a, y);
}

// round 17
// speedup vs baseline: 1.0484x; 1.0484x over previous
#include <cuda_runtime.h>
#include <cuda_fp16.h>
#include <math.h>
#include <cstdint>

#define NB 32
#define NN 512

// Scratch (device globals; allocation-free per harness rules).
__device__ __align__(16) __half g_c16[(size_t)NB * NN * NN];  // fp16 c [m][k]
__device__ __align__(16) __half g_a16[(size_t)NB * NN * NN];  // fp16 a [j][n] row-major
__device__ __align__(16) float  g_G[(size_t)NB * NN * NN];    // G = c @ a (fp32)

// ---------------------------------------------------------------------------
__device__ __forceinline__ uint32_t smem_u32(const void* p) {
    uint32_t a;
    asm("{ .reg .u64 t; cvta.to.shared.u64 t, %1; cvt.u32.u64 %0, t; }" : "=r"(a) : "l"(p));
    return a;
}
__device__ __forceinline__ void cp_async16(uint32_t saddr, const void* gaddr) {
    asm volatile("cp.async.cg.shared.global [%0], [%1], 16;" :: "r"(saddr), "l"(gaddr) : "memory");
}
__device__ __forceinline__ void cp_commit() { asm volatile("cp.async.commit_group;" ::: "memory"); }
template <int N>
__device__ __forceinline__ void cp_wait() {
    asm volatile("cp.async.wait_group %0;" :: "n"(N) : "memory");
}

__device__ __forceinline__ void ldsm_x4(uint32_t* r, uint32_t addr) {
    asm volatile("ldmatrix.sync.aligned.m8n8.x4.shared.b16 {%0,%1,%2,%3}, [%4];"
                 : "=r"(r[0]), "=r"(r[1]), "=r"(r[2]), "=r"(r[3]) : "r"(addr));
}
__device__ __forceinline__ void ldsm_x4_t(uint32_t* r, uint32_t addr) {
    asm volatile("ldmatrix.sync.aligned.m8n8.x4.trans.shared.b16 {%0,%1,%2,%3}, [%4];"
                 : "=r"(r[0]), "=r"(r[1]), "=r"(r[2]), "=r"(r[3]) : "r"(addr));
}
__device__ __forceinline__ void mma_fp16(float* d, const uint32_t* a, const uint32_t* b) {
    asm volatile(
        "mma.sync.aligned.m16n8k16.row.col.f32.f16.f16.f32 "
        "{%0,%1,%2,%3}, {%4,%5,%6,%7}, {%8,%9}, {%0,%1,%2,%3};"
        : "+f"(d[0]), "+f"(d[1]), "+f"(d[2]), "+f"(d[3])
        : "r"(a[0]), "r"(a[1]), "r"(a[2]), "r"(a[3]), "r"(b[0]), "r"(b[1]));
}

// temp arrives as 1-elem scalar, int32 or float32 bits; decode robustly.
__device__ __forceinline__ float decode_scalar(const int* p) {
    int ib = *p;
    float f = __int_as_float(ib);
    if (isfinite(f) && fabsf(f) > 1e-30f && fabsf(f) < 1e30f) return f;
    return (float)ib;
}

// ---------------------------------------------------------------------------
// Fused c + step0 (verbatim R13).
// ---------------------------------------------------------------------------
__global__ void __launch_bounds__(256) cstep0_kernel(
    const float* __restrict__ x, const float* __restrict__ w1,
    const float* __restrict__ b1, const float* __restrict__ w2,
    const float* __restrict__ lr, const int* __restrict__ temp_p)
{
    int b  = blockIdx.y;
    int i0 = blockIdx.x * 8;
    __shared__ float xs[NN];
    __shared__ float sw1a[16], sw1b[16], sb1[16], sw2[16];
    __shared__ float red[8];
    __shared__ float sS, sM, sT;
    const int t    = threadIdx.x;
    const int lane = t & 31;
    const int wid  = t >> 5;
    if (t < 16) {
        sw1a[t] = w1[t * 2 + 0];
        sw1b[t] = w1[t * 2 + 1];
        sb1[t]  = b1[t];
        sw2[t]  = w2[t];
    }
    xs[t]       = x[b * NN + t];
    xs[t + 256] = x[b * NN + t + 256];
    __syncthreads();

    const float lr_abs = fabsf(lr[0]);
    const float invT   = 1.f / decode_scalar(temp_p);
    const float invN   = 1.f / (float)NN;

    for (int ii = 0; ii < 8; ii++) {
        int i = i0 + ii;
        float xi = xs[i];
        size_t rowoff = ((size_t)b * NN + i) * NN;

        float sv[2];
#pragma unroll
        for (int q = 0; q < 2; q++) {
            float xj = xs[t + q * 256];
            float s = 0.f;
#pragma unroll
            for (int o = 0; o < 16; o++) {
                float h1 = fmaxf(fmaf(sw1a[o], xi, fmaf(sw1b[o], xj, sb1[o])), 0.f);
                float h2 = fmaxf(fmaf(sw1a[o], xj, fmaf(sw1b[o], xi, sb1[o])), 0.f);
                s = fmaf(sw2[o], h1 - h2, s);
            }
            __half h = __float2half(s);
            g_c16[rowoff + t + q * 256] = h;
            sv[q] = __half2float(h);
        }

        float v = sv[0] + sv[1];
#pragma unroll
        for (int o = 16; o > 0; o >>= 1) v += __shfl_xor_sync(0xffffffffu, v, o);
        if (lane == 0) red[wid] = v;
        __syncthreads();
        if (wid == 0) {
            float s8 = (lane < 8) ? red[lane] : 0.f;
#pragma unroll
            for (int o = 4; o > 0; o >>= 1) s8 += __shfl_xor_sync(0xffffffffu, s8, o);
            if (lane == 0) sS = s8;
        }
        __syncthreads();
        const float S = sS;

        float l0 = (invN - lr_abs * S * (1.f - (2.f * t + 1.f) * invN)) * invT;
        float l1 = (invN - lr_abs * S * (1.f - (2.f * (t + 256) + 1.f) * invN)) * invT;

        float m = fmaxf(l0, l1);
#pragma unroll
        for (int o = 16; o > 0; o >>= 1) m = fmaxf(m, __shfl_xor_sync(0xffffffffu, m, o));
        __syncthreads();
        if (lane == 0) red[wid] = m;
        __syncthreads();
        if (wid == 0) {
            float m8 = (lane < 8) ? red[lane] : -INFINITY;
#pragma unroll
            for (int o = 4; o > 0; o >>= 1) m8 = fmaxf(m8, __shfl_xor_sync(0xffffffffu, m8, o));
            if (lane == 0) sM = m8;
        }
        __syncthreads();
        const float M = sM;

        float e0 = __expf(l0 - M);
        float e1 = __expf(l1 - M);
        float se = e0 + e1;
#pragma unroll
        for (int o = 16; o > 0; o >>= 1) se += __shfl_xor_sync(0xffffffffu, se, o);
        __syncthreads();
        if (lane == 0) red[wid] = se;
        __syncthreads();
        if (wid == 0) {
            float t8 = (lane < 8) ? red[lane] : 0.f;
#pragma unroll
            for (int o = 4; o > 0; o >>= 1) t8 += __shfl_xor_sync(0xffffffffu, t8, o);
            if (lane == 0) sT = t8;
        }
        __syncthreads();
        const float invTot = 1.f / sT;

        g_a16[rowoff + t]       = __float2half(e0 * invTot);
        g_a16[rowoff + t + 256] = __float2half(e1 * invTot);
        __syncthreads();
    }
}

// ---------------------------------------------------------------------------
// Batched GEMM: G = c @ a, single-product fp16 mma.sync.
// Fine tiles: 64x128 per CTA, 128 thr (4 warps: 2M x 2N, warp tile 32x64),
// 4 CTAs/SM, 6-stage cp.async ring, K=16 per stage.
// Graded tail waits: at iter s we certify groups 0..s complete exactly
// (wait4 while commits continue; wait 31-s for s in 28..31).
// Per-element K accumulation order identical to R13 -> G bitwise identical.
// ---------------------------------------------------------------------------
#define PA 24
#define PB 136
#define A_TILE_B (64 * PA * 2)         // 3072 B
#define B_TILE_B (16 * PB * 2)         // 4352 B
#define STAGE_B  (A_TILE_B + B_TILE_B) // 7424
#define NSTAGE 6
#define GEMM_SMEM (NSTAGE * STAGE_B)   // 44544

__global__ void __launch_bounds__(128, 4) gemm_mma_kernel()
{
    extern __shared__ __align__(16) char sm[];
    const int b  = blockIdx.z;
    const int m0 = blockIdx.y * 64;
    const int n0 = blockIdx.x * 128;
    const int tid  = threadIdx.x;
    const int wid  = tid >> 5;
    const int lane = tid & 31;

    const __half* Amat = g_c16 + (size_t)b * NN * NN;
    const __half* Bmat = g_a16 + (size_t)b * NN * NN;

    const uint32_t smbase = smem_u32(sm);

    auto load_stage = [&](int ks16) {
        const int k0 = ks16 * 16;
        const uint32_t sb = smbase + (ks16 % NSTAGE) * STAGE_B;
        {
            int r = tid >> 1;              // 0..63
            int c = tid & 1;               // 0..1
            cp_async16(sb + (uint32_t)(r * (PA * 2) + c * 16),
                       Amat + (size_t)(m0 + r) * NN + k0 + c * 8);
        }
#pragma unroll
        for (int it = 0; it < 2; it++) {
            int idx = it * 128 + tid;      // 0..255
            int r   = idx >> 4;            // 0..15
            int c   = idx & 15;            // 0..15
            cp_async16(sb + A_TILE_B + (uint32_t)(r * (PB * 2) + c * 16),
                       Bmat + (size_t)(k0 + r) * NN + n0 + c * 8);
        }
        cp_commit();
    };

    const int wm = wid & 1;                // M half (32 rows)
    const int wn = wid >> 1;               // N half (64 cols)

    float acc[2][8][4];
#pragma unroll
    for (int mi = 0; mi < 2; mi++)
#pragma unroll
        for (int ni = 0; ni < 8; ni++)
#pragma unroll
            for (int q = 0; q < 4; q++) acc[mi][ni][q] = 0.f;

    const int l_r = lane & 15;
    const int l_c = 8 * (lane >> 4);

#pragma unroll
    for (int s = 0; s < NSTAGE - 1; s++) load_stage(s);

    for (int s = 0; s < 32; s++) {
        // Certify group s complete: committed = min(s+5, 32) groups; allowed
        // pending = committed - (s+1).
        if (s < 28)      cp_wait<4>();
        else if (s == 28) cp_wait<3>();
        else if (s == 29) cp_wait<2>();
        else if (s == 30) cp_wait<1>();
        else              cp_wait<0>();
        __syncthreads();

        const uint32_t sb = smbase + (s % NSTAGE) * STAGE_B;
        uint32_t ah[2][4];
#pragma unroll
        for (int mi = 0; mi < 2; mi++) {
            uint32_t addr = sb + (wm * 32 + mi * 16 + l_r) * (PA * 2) + l_c * 2;
            ldsm_x4(ah[mi], addr);
        }
        uint32_t bh[8][2];
#pragma unroll
        for (int nh = 0; nh < 2; nh++) {
#pragma unroll
            for (int t16 = 0; t16 < 2; t16++) {
                uint32_t addr = sb + A_TILE_B +
                                l_r * (PB * 2) + (wn * 64 + nh * 32 + t16 * 16 + l_c) * 2;
                uint32_t r4[4];
                ldsm_x4_t(r4, addr);
                int base = nh * 4 + t16 * 2;
                bh[base][0] = r4[0];     bh[base][1] = r4[1];
                bh[base + 1][0] = r4[2]; bh[base + 1][1] = r4[3];
            }
        }
#pragma unroll
        for (int mi = 0; mi < 2; mi++)
#pragma unroll
            for (int ni = 0; ni < 8; ni++)
                mma_fp16(acc[mi][ni], ah[mi], bh[ni]);

        if (s + NSTAGE - 1 < 32) load_stage(s + NSTAGE - 1);
        __syncthreads();
    }
    cp_wait<0>();

    float* Gb = g_G + (size_t)b * NN * NN;
    const int g  = lane >> 2;
    const int t4 = lane & 3;
#pragma unroll
    for (int mi = 0; mi < 2; mi++) {
        int r0 = m0 + wm * 32 + mi * 16 + g;
#pragma unroll
        for (int ni = 0; ni < 8; ni++) {
            int col = n0 + wn * 64 + ni * 8 + t4 * 2;
            *(float2*)(Gb + (size_t)r0 * NN + col) =
                make_float2(acc[mi][ni][0], acc[mi][ni][1]);
            *(float2*)(Gb + (size_t)(r0 + 8) * NN + col) =
                make_float2(acc[mi][ni][2], acc[mi][ni][3]);
        }
    }
}

// ---------------------------------------------------------------------------
// Epilogue fused (verbatim R13): warp per row; reads G + a(fp16);
// writes a' fp16 (+ fp32 a' on last step).
// ---------------------------------------------------------------------------
__global__ void __launch_bounds__(256) epi_fuse_kernel(
    float* __restrict__ a_out, const float* __restrict__ lr,
    const int* __restrict__ temp_p, int last)
{
    const int row  = blockIdx.x * 8 + (threadIdx.x >> 5);
    const int lane = threadIdx.x & 31;
    const size_t base = (size_t)row * NN + lane * 16;
    const float* Gr = g_G + base;

    float g[16];
#pragma unroll
    for (int q = 0; q < 4; q++) {
        float4 vg = *(const float4*)(Gr + q * 4);
        g[q * 4 + 0] = vg.x; g[q * 4 + 1] = vg.y; g[q * 4 + 2] = vg.z; g[q * 4 + 3] = vg.w;
    }

    union U16 { uint4 u4[2]; __half h[16]; };
    U16 ua;
    ua.u4[0] = *(const uint4*)(g_a16 + base);
    ua.u4[1] = *(const uint4*)(g_a16 + base + 8);

    float av[16];
#pragma unroll
    for (int c = 0; c < 16; c++) av[c] = __half2float(ua.h[c]);

    float p[16];
    float run = 0.f;
#pragma unroll
    for (int c = 0; c < 16; c++) { run += g[c]; p[c] = run; }
    float inc = run;
#pragma unroll
    for (int o = 1; o < 32; o <<= 1) {
        float n = __shfl_up_sync(0xffffffffu, inc, o);
        if (lane >= o) inc += n;
    }
    const float excl = inc - run;

    const float lr_abs = fabsf(lr[0]);
    const float invT   = 1.f / decode_scalar(temp_p);

    float lo[16];
    float mx = -INFINITY;
#pragma unroll
    for (int c = 0; c < 16; c++) {
        float cum = excl + p[c];
        float l = (av[c] - lr_abs * (g[c] - 2.f * cum)) * invT;
        lo[c] = l;
        mx = fmaxf(mx, l);
    }
#pragma unroll
    for (int o = 16; o > 0; o >>= 1) mx = fmaxf(mx, __shfl_xor_sync(0xffffffffu, mx, o));

    float s = 0.f;
#pragma unroll
    for (int c = 0; c < 16; c++) { lo[c] = __expf(lo[c] - mx); s += lo[c]; }
#pragma unroll
    for (int o = 16; o > 0; o >>= 1) s += __shfl_xor_sync(0xffffffffu, s, o);
    const float invS = 1.f / s;

    U16 oa;
#pragma unroll
    for (int c = 0; c < 16; c++) {
        float v = lo[c] * invS;
        oa.h[c] = __float2half(v);
        lo[c] = v;
    }
    *(uint4*)(g_a16 + base)     = oa.u4[0];
    *(uint4*)(g_a16 + base + 8) = oa.u4[1];

    if (last) {
        float* ar = a_out + base;
#pragma unroll
        for (int q = 0; q < 4; q++)
            *(float4*)(ar + q * 4) = make_float4(lo[q * 4 + 0], lo[q * 4 + 1],
                                                 lo[q * 4 + 2], lo[q * 4 + 3]);
    }
}

// ---------------------------------------------------------------------------
// y[b,k] = sum_i x[b,i] * a[b,i,k]; 16 i-chunks per batch + atomicAdd.
// (verbatim R13)
// ---------------------------------------------------------------------------
__global__ void init_y_kernel(float* __restrict__ y)
{
    y[blockIdx.x * 1024 + threadIdx.x] = 0.f;
}

__global__ void __launch_bounds__(512) y_kernel(
    const float* __restrict__ x, const float* __restrict__ a, float* __restrict__ y)
{
    int b  = blockIdx.x;
    int ch = blockIdx.y;
    int k  = threadIdx.x;
    __shared__ float xs[32];
    if (k < 32) xs[k] = x[b * NN + ch * 32 + k];
    __syncthreads();
    const float* ab = a + (size_t)b * NN * NN + (size_t)ch * 32 * NN;
    float a0 = 0.f, a1 = 0.f, a2 = 0.f, a3 = 0.f;
#pragma unroll
    for (int i = 0; i < 32; i += 4) {
        a0 = fmaf(xs[i + 0], ab[(size_t)(i + 0) * NN + k], a0);
        a1 = fmaf(xs[i + 1], ab[(size_t)(i + 1) * NN + k], a1);
        a2 = fmaf(xs[i + 2], ab[(size_t)(i + 2) * NN + k], a2);
        a3 = fmaf(xs[i + 3], ab[(size_t)(i + 3) * NN + k], a3);
    }
    atomicAdd(&y[b * NN + k], (a0 + a1) + (a2 + a3));
}

// ---------------------------------------------------------------------------
extern "C" void kernel_launch(void* const* d_in, const int* in_sizes, int n_in,
                              void* d_out, int out_size)
{
    const float* x   = (const float*)d_in[0];
    const float* w1  = (const float*)d_in[1];
    const float* b1  = (const float*)d_in[2];
    const float* w2  = (const float*)d_in[3];
    // d_in[4] = b2 (cancels in c - c^T), d_in[6] = steps (fixed at 8)
    const float* lr  = (const float*)d_in[5];
    const int* temp_p = (const int*)d_in[7];

    float* y = (float*)d_out;              // (32,1,512)
    float* a = (float*)d_out + NB * NN;    // (32,512,512), written on last step

    cudaFuncSetAttribute(gemm_mma_kernel, cudaFuncAttributeMaxDynamicSharedMemorySize, GEMM_SMEM);

    cstep0_kernel<<<dim3(NN / 8, NB), 256>>>(x, w1, b1, w2, lr, temp_p);

    for (int s = 0; s < 7; s++) {
        gemm_mma_kernel<<<dim3(4, 8, NB), 128, GEMM_SMEM>>>();
        epi_fuse_kernel<<<NB * NN / 8, 256>>>(a, lr, temp_p, (s == 6) ? 1 : 0);
    }

    init_y_kernel<<<NB * NN / 1024, 1024>>>(y);
    y_kernel<<<dim3(NB, 16), 512>>>(x, a, y);
}